// round 1
// baseline (speedup 1.0000x reference)
#include <cuda_runtime.h>
#include <cuda_bf16.h>
#include <math.h>

#define NCL 10
#define DD 64
#define TPB1 128

// final cluster centers from the iterative kernel
__device__ float g_cc[NCL * DD];

// ---------------- helpers ----------------

__device__ __forceinline__ void cp_async16(float* smem_dst, const float* gsrc) {
    unsigned d = (unsigned)__cvta_generic_to_shared(smem_dst);
    asm volatile("cp.async.cg.shared.global [%0], [%1], 16;\n" :: "r"(d), "l"(gsrc));
}

// Stage an [R, L] row-major weight matrix into smem with a float4-preserving
// XOR swizzle: element (r, c) stored at r*L + (c ^ ((r<<2) & (L-4))).
// Guarantees conflict-free LDS.128 when lanes read consecutive rows r.
__device__ __forceinline__ void stage_w(const float* __restrict__ g, float* __restrict__ s,
                                        int R, int L, int tid, int T) {
    int total4 = (R * L) >> 2;
    for (int e4 = tid; e4 < total4; e4 += T) {
        int e = e4 << 2;
        int r = e / L;
        int c = e & (L - 1);
        float4 v = *reinterpret_cast<const float4*>(g + e);
        *reinterpret_cast<float4*>(s + r * L + (c ^ ((r << 2) & (L - 4)))) = v;
    }
}

// acc[n] = sum_c W[r][c] * act[n*L + c]  (W swizzle-stored in smem)
// n-blocked: one weight LDS.128 feeds 10*4 FMAs; act reads are warp broadcasts.
__device__ __forceinline__ void gemm_row10(const float* __restrict__ Wsm,
                                           const float* __restrict__ act,
                                           int r, int L, float* acc) {
#pragma unroll
    for (int n = 0; n < NCL; n++) acc[n] = 0.f;
    const int sw = (r << 2) & (L - 4);
#pragma unroll 4
    for (int c = 0; c < L; c += 4) {
        float4 w = *reinterpret_cast<const float4*>(Wsm + r * L + (c ^ sw));
#pragma unroll
        for (int n = 0; n < NCL; n++) {
            float4 a = *reinterpret_cast<const float4*>(act + n * L + c);
            acc[n] = fmaf(w.x, a.x, acc[n]);
            acc[n] = fmaf(w.y, a.y, acc[n]);
            acc[n] = fmaf(w.z, a.z, acc[n]);
            acc[n] = fmaf(w.w, a.w, acc[n]);
        }
    }
}

// ---------------- kernel 1: iterative slot attention (1 block) ----------------

__global__ void __launch_bounds__(TPB1) iter_kernel(
    const float* __restrict__ cc0,
    const float* __restrict__ Wk, const float* __restrict__ bk,
    const float* __restrict__ Wq, const float* __restrict__ bq,
    const float* __restrict__ Wv, const float* __restrict__ bv,
    const float* __restrict__ ccg, const float* __restrict__ ccb,
    const float* __restrict__ Wih, const float* __restrict__ Whh,
    const float* __restrict__ bih, const float* __restrict__ bhh,
    const float* __restrict__ g_lng, const float* __restrict__ g_lnb,
    const float* __restrict__ W1, const float* __restrict__ b1,
    const float* __restrict__ W2, const float* __restrict__ b2)
{
    extern __shared__ float sm[];
    float* Wq_s   = sm;               // 4096
    float* Wih_s  = Wq_s + 4096;      // 12288  (holds Wk during init)
    float* Whh_s  = Wih_s + 12288;    // 12288  (holds Wv during init)
    float* W1_s   = Whh_s + 12288;    // 8192
    float* W2_s   = W1_s + 8192;      // 8192
    float* cc_s   = W2_s + 8192;      // 640
    float* ccp_s  = cc_s + 640;       // 640
    float* kk_s   = ccp_s + 640;      // 640
    float* vv_s   = kk_s + 640;       // 640
    float* lnx_s  = vv_s + 640;       // 640 (LN output buffer)
    float* q_s    = lnx_s + 640;      // 640
    float* VW_s   = q_s + 640;        // 1920 (v @ W_ih^T, layout [n][192])
    float* gh_s   = VW_s + 1920;      // 1920 (layout [n][192])
    float* hh_s   = gh_s + 1920;      // 1280 (layout [n][128])
    float* attn_s = hh_s + 1280;      // 100
    float* mv_s   = attn_s + 100;     // 20

    const int tid = threadIdx.x;

    // load initial cc, stage Wk/Wv/Wq
    for (int e = tid; e < NCL * DD; e += TPB1) cc_s[e] = cc0[e];
    stage_w(Wk, Wih_s, 64, 64, tid, TPB1);
    stage_w(Wv, Whh_s, 64, 64, tid, TPB1);
    stage_w(Wq, Wq_s, 64, 64, tid, TPB1);
    __syncthreads();

    // k, v (computed once)
    if (tid < 64) {
        float acc[NCL];
        gemm_row10(Wih_s, cc_s, tid, 64, acc);
        float b = bk[tid];
#pragma unroll
        for (int n = 0; n < NCL; n++) kk_s[n * 64 + tid] = acc[n] + b;
        gemm_row10(Whh_s, cc_s, tid, 64, acc);
        b = bv[tid];
#pragma unroll
        for (int n = 0; n < NCL; n++) vv_s[n * 64 + tid] = acc[n] + b;
    }
    __syncthreads();

    // stage the big weights (overwrites Wk/Wv staging areas)
    stage_w(Wih, Wih_s, 192, 64, tid, TPB1);
    stage_w(Whh, Whh_s, 192, 64, tid, TPB1);
    stage_w(W1, W1_s, 128, 64, tid, TPB1);
    stage_w(W2, W2_s, 64, 128, tid, TPB1);
    __syncthreads();

    // VW[m][r] = sum_j v[m][j] * W_ih[r][j]  (iteration-invariant hoist)
    for (int r = tid; r < 192; r += TPB1) {
        float acc[NCL];
        gemm_row10(Wih_s, vv_s, r, 64, acc);
#pragma unroll
        for (int n = 0; n < NCL; n++) VW_s[n * 192 + r] = acc[n];
    }
    __syncthreads();

    for (int it = 0; it < 3; ++it) {
        // cc_prev copy + LN(cc_g/cc_b) stats
        for (int e = tid; e < 640; e += TPB1) ccp_s[e] = cc_s[e];
        if (tid < NCL) {
            float m = 0.f, s2 = 0.f;
#pragma unroll 8
            for (int j = 0; j < 64; j++) {
                float x = cc_s[tid * 64 + j];
                m += x; s2 = fmaf(x, x, s2);
            }
            m *= (1.f / 64.f);
            s2 = s2 * (1.f / 64.f) - m * m;
            mv_s[2 * tid] = m;
            mv_s[2 * tid + 1] = rsqrtf(s2 + 1e-5f);
        }
        __syncthreads();
        for (int e = tid; e < 640; e += TPB1) {
            int n = e >> 6, i = e & 63;
            lnx_s[e] = (cc_s[e] - mv_s[2 * n]) * mv_s[2 * n + 1] * ccg[i] + ccb[i];
        }
        __syncthreads();

        // q rows on t<64; gh rows 0..63 on t>=64; then gh rows 64..191 on all
        if (tid < 64) {
            float acc[NCL];
            gemm_row10(Wq_s, lnx_s, tid, 64, acc);
            float b = bq[tid];
#pragma unroll
            for (int n = 0; n < NCL; n++) q_s[n * 64 + tid] = acc[n] + b;
        } else {
            int r = tid - 64;
            float acc[NCL];
            gemm_row10(Whh_s, ccp_s, r, 64, acc);
            float b = bhh[r];
#pragma unroll
            for (int n = 0; n < NCL; n++) gh_s[n * 192 + r] = acc[n] + b;
        }
        {
            int r = 64 + tid;
            float acc[NCL];
            gemm_row10(Whh_s, ccp_s, r, 64, acc);
            float b = bhh[r];
#pragma unroll
            for (int n = 0; n < NCL; n++) gh_s[n * 192 + r] = acc[n] + b;
        }
        __syncthreads();

        // raw attention logits
        if (tid < 100) {
            int n = tid / 10, m = tid % 10;
            float s = 0.f;
#pragma unroll 8
            for (int j = 0; j < 64; j++)
                s = fmaf(kk_s[n * 64 + j], q_s[m * 64 + j], s);
            attn_s[n * 10 + m] = s * 0.125f;  // d^-0.5
        }
        __syncthreads();
        // softmax over axis 0 (columns), + EPS
        if (tid < NCL) {
            int m = tid;
            float a[NCL], mx = -1e30f;
#pragma unroll
            for (int n = 0; n < NCL; n++) { a[n] = attn_s[n * 10 + m]; mx = fmaxf(mx, a[n]); }
            float ss = 0.f;
#pragma unroll
            for (int n = 0; n < NCL; n++) { a[n] = expf(a[n] - mx); ss += a[n]; }
            float inv = 1.f / ss;
#pragma unroll
            for (int n = 0; n < NCL; n++) attn_s[n * 10 + m] = a[n] * inv + 1e-8f;
        }
        __syncthreads();
        // renormalize over axis -1 (rows)
        if (tid < NCL) {
            int n = tid;
            float ss = 0.f;
#pragma unroll
            for (int m = 0; m < NCL; m++) ss += attn_s[n * 10 + m];
            float inv = 1.f / ss;
#pragma unroll
            for (int m = 0; m < NCL; m++) attn_s[n * 10 + m] *= inv;
        }
        __syncthreads();

        // GRU: gi = attn @ VW + b_ih ; gh precomputed
        for (int e = tid; e < 640; e += TPB1) {
            int n = e >> 6, i = e & 63;
            float gi0 = bih[i], gi1 = bih[64 + i], gi2 = bih[128 + i];
#pragma unroll
            for (int m = 0; m < NCL; m++) {
                float a = attn_s[n * 10 + m];
                const float* vw = VW_s + m * 192;
                gi0 = fmaf(a, vw[i], gi0);
                gi1 = fmaf(a, vw[64 + i], gi1);
                gi2 = fmaf(a, vw[128 + i], gi2);
            }
            float h0 = gh_s[n * 192 + i];
            float h1 = gh_s[n * 192 + 64 + i];
            float h2 = gh_s[n * 192 + 128 + i];
            float r = 1.f / (1.f + expf(-(gi0 + h0)));
            float z = 1.f / (1.f + expf(-(gi1 + h1)));
            float nn = tanhf(gi2 + r * h2);
            cc_s[e] = (1.f - z) * nn + z * ccp_s[e];
        }
        __syncthreads();

        // LN(ln_g/ln_b) on new cc
        if (tid < NCL) {
            float m = 0.f, s2 = 0.f;
#pragma unroll 8
            for (int j = 0; j < 64; j++) {
                float x = cc_s[tid * 64 + j];
                m += x; s2 = fmaf(x, x, s2);
            }
            m *= (1.f / 64.f);
            s2 = s2 * (1.f / 64.f) - m * m;
            mv_s[2 * tid] = m;
            mv_s[2 * tid + 1] = rsqrtf(s2 + 1e-5f);
        }
        __syncthreads();
        for (int e = tid; e < 640; e += TPB1) {
            int n = e >> 6, i = e & 63;
            lnx_s[e] = (cc_s[e] - mv_s[2 * n]) * mv_s[2 * n + 1] * g_lng[i] + g_lnb[i];
        }
        __syncthreads();

        // MLP hidden: 128 rows
        {
            int r = tid;
            float acc[NCL];
            gemm_row10(W1_s, lnx_s, r, 64, acc);
            float b = b1[r];
#pragma unroll
            for (int n = 0; n < NCL; n++) hh_s[n * 128 + r] = fmaxf(acc[n] + b, 0.f);
        }
        __syncthreads();
        // MLP out + residual
        if (tid < 64) {
            float acc[NCL];
            gemm_row10(W2_s, hh_s, tid, 128, acc);
            float b = b2[tid];
#pragma unroll
            for (int n = 0; n < NCL; n++) cc_s[n * 64 + tid] += acc[n] + b;
        }
        __syncthreads();
    }

    for (int e = tid; e < 640; e += TPB1) g_cc[e] = cc_s[e];
}

// ---------------- kernel 2: per-slot MLP + max (4096 blocks) ----------------

__global__ void __launch_bounds__(64) slot_kernel(
    const float* __restrict__ Wa, const float* __restrict__ ba,
    const float* __restrict__ Wb, const float* __restrict__ bb,
    float* __restrict__ out)
{
    __shared__ float bufA[4096];
    __shared__ float bufB[4096];
    __shared__ float cc2[640];
    __shared__ float hsm[640];

    const int s = blockIdx.x;
    const int t = threadIdx.x;
    const float* wa = Wa + (size_t)s * 4096;
    const float* wb = Wb + (size_t)s * 4096;

    // double-buffered streaming loads (swizzled dst), Wb in flight during phase 1
#pragma unroll
    for (int k = 0; k < 16; ++k) {
        int e = (t + 64 * k) * 4;
        int r = e >> 6, c = e & 63;
        cp_async16(&bufA[r * 64 + (c ^ ((r << 2) & 60))], wa + e);
    }
    asm volatile("cp.async.commit_group;\n" ::: "memory");
#pragma unroll
    for (int k = 0; k < 16; ++k) {
        int e = (t + 64 * k) * 4;
        int r = e >> 6, c = e & 63;
        cp_async16(&bufB[r * 64 + (c ^ ((r << 2) & 60))], wb + e);
    }
    asm volatile("cp.async.commit_group;\n" ::: "memory");

    for (int e = t; e < 640; e += 64) cc2[e] = g_cc[e];

    asm volatile("cp.async.wait_group 1;\n" ::: "memory");
    __syncthreads();

    float acc[NCL];
    // h[n][t] = relu(Wa[t] . cc[n] + ba[s][t])
    gemm_row10(bufA, cc2, t, 64, acc);
    {
        float b = ba[s * 64 + t];
#pragma unroll
        for (int n = 0; n < NCL; n++) hsm[n * 64 + t] = fmaxf(acc[n] + b, 0.f);
    }

    asm volatile("cp.async.wait_group 0;\n" ::: "memory");
    __syncthreads();

    // out[n][t] = Wb[t] . h[n] + bb[s][t]; reduce max over n
    gemm_row10(bufB, hsm, t, 64, acc);
    float b = bb[s * 64 + t];
    float m = -3.4e38f;
#pragma unroll
    for (int n = 0; n < NCL; n++) m = fmaxf(m, acc[n] + b);
    out[s * 64 + t] = m;
}

// ---------------- launch ----------------

extern "C" void kernel_launch(void* const* d_in, const int* in_sizes, int n_in,
                              void* d_out, int out_size) {
    const float* cc0 = (const float*)d_in[0];
    const float* Wk  = (const float*)d_in[1];
    const float* bk  = (const float*)d_in[2];
    const float* Wq  = (const float*)d_in[3];
    const float* bq  = (const float*)d_in[4];
    const float* Wv  = (const float*)d_in[5];
    const float* bv  = (const float*)d_in[6];
    const float* ccg = (const float*)d_in[7];
    const float* ccb = (const float*)d_in[8];
    const float* Wih = (const float*)d_in[9];
    const float* Whh = (const float*)d_in[10];
    const float* bih = (const float*)d_in[11];
    const float* bhh = (const float*)d_in[12];
    const float* lng = (const float*)d_in[13];
    const float* lnb = (const float*)d_in[14];
    const float* W1  = (const float*)d_in[15];
    const float* b1  = (const float*)d_in[16];
    const float* W2  = (const float*)d_in[17];
    const float* b2  = (const float*)d_in[18];
    const float* Wa  = (const float*)d_in[19];
    const float* ba  = (const float*)d_in[20];
    const float* Wb  = (const float*)d_in[21];
    const float* bb  = (const float*)d_in[22];
    float* out = (float*)d_out;

    constexpr int SMEM1 = 54136 * 4;  // 216,544 B < 227 KB opt-in
    cudaFuncSetAttribute(iter_kernel, cudaFuncAttributeMaxDynamicSharedMemorySize, SMEM1);

    iter_kernel<<<1, TPB1, SMEM1>>>(cc0, Wk, bk, Wq, bq, Wv, bv, ccg, ccb,
                                    Wih, Whh, bih, bhh, lng, lnb, W1, b1, W2, b2);
    slot_kernel<<<4096, 64>>>(Wa, ba, Wb, bb, out);
}